// round 5
// baseline (speedup 1.0000x reference)
#include <cuda_runtime.h>

#define MM   128   // padded image side
#define NP   64    // patch side
#define NC   4     // channels / positions
#define C0   32    // (M - N) / 2
#define RB   16    // rows per thread (contiguous band)

// block (2, 64, 4): tx = channel PAIR (fastest), ty = output column,
// tz = row band. A warp = 2 channel-pairs x 16 consecutive columns:
//  - float2 stores form one contiguous 256B run (full sectors)
//  - horizontal taps are shared between column-neighbor lanes via shfl.down(2)
__global__ __launch_bounds__(512, 3)
void extract_patches_kernel(const float* __restrict__ img,
                            const float* __restrict__ pos,
                            float* __restrict__ out)
{
    const int b = blockIdx.x;
    const float* I = img + (size_t)b * (MM * MM);

    // Stage the 8 position scalars: layout (B,1,2,C); dim0 = ox, dim1 = oy.
    __shared__ float spos[2 * NC];
    const int lid = threadIdx.x + 2 * threadIdx.y + 128 * threadIdx.z;
    if (lid < 2 * NC)
        spos[lid] = pos[(size_t)b * (2 * NC) + lid];
    __syncthreads();

    const int col = threadIdx.y;                 // output column j in [0, 64)
    const int i0  = threadIdx.z * RB;            // first row of this band
    const int cb  = threadIdx.x * 2;             // first of 2 owned channels
    const bool edge = ((col & 15) == 15);        // last column-lane in warp

    // Per-channel setup. xi is derived from a column-UNIFORM base so that
    // xi(col+1) == xi(col)+1 exactly -> shuffle tap sharing is consistent.
    // wx may then fall at -eps or 1+eps; bilinear extrapolates continuously,
    // so the value still matches the reference to O(eps).
    float wx[2], hprev[2], yif[2], oyv[2];
    int   off[2];
#pragma unroll
    for (int u = 0; u < 2; u++) {
        float ox = spos[cb + u];
        oyv[u]   = spos[NC + cb + u];

        int   xib = (int)floorf((float)C0 + ox) + col;   // uniform base + col
        float xx  = (float)(col + C0) + ox;              // reference arithmetic
        wx[u]     = xx - (float)xib;

        float yy = (float)(i0 + C0) + oyv[u];
        float y0 = floorf(yy);
        yif[u]   = y0;
        int yi   = (int)y0;

        // SHIFT_MAX=20, c0=32: indices in [11,52]; deepest access stays
        // well inside 128 -> the reference valid-mask is always true.
        off[u] = yi * MM + xib;
        float a0 = __ldg(I + off[u]);
        float a1 = __shfl_down_sync(0xffffffffu, a0, 2);
        if (edge) a1 = __ldg(I + off[u] + 1);
        hprev[u] = fmaf(a1 - a0, wx[u], a0);   // H(top row)
    }

    // Output: (B, 64, 64, 4); channels cb..cb+1 at column `col`,
    // rows i0..i0+RB-1. Warp-contiguous float2 stores.
    float* ob = out + ((size_t)b * (NP * NP) + (size_t)i0 * NP + col) * NC + cb;

    // Walk RB contiguous rows; each step loads ONE new bottom tap per channel
    // (right tap via shuffle) and reuses hprev as the top H-row.
#pragma unroll
    for (int k = 0; k < RB; k++) {
        float2 res;
#pragma unroll
        for (int u = 0; u < 2; u++) {
            off[u] += MM;
            float b0 = __ldg(I + off[u]);
            float b1 = __shfl_down_sync(0xffffffffu, b0, 2);
            if (edge) b1 = __ldg(I + off[u] + 1);
            float hnew = fmaf(b1 - b0, wx[u], b0);      // H(bottom row)

            float yy = (float)(i0 + k + C0) + oyv[u];
            float wy = yy - (yif[u] + (float)k);

            float r  = fmaf(hnew - hprev[u], wy, hprev[u]);
            hprev[u] = hnew;
            if (u == 0) res.x = r; else res.y = r;
        }
        // Streaming store: output never re-read; full-sector coverage.
        __stcs(reinterpret_cast<float2*>(ob + (size_t)k * (NP * NC)), res);
    }
}

extern "C" void kernel_launch(void* const* d_in, const int* in_sizes, int n_in,
                              void* d_out, int out_size)
{
    const float* img = (const float*)d_in[0];   // padded_obj (B,128,128,1)
    const float* pos = (const float*)d_in[1];   // positions  (B,1,2,4)
    float* out = (float*)d_out;                 // (B,64,64,4)

    int B = in_sizes[0] / (MM * MM);
    dim3 block(2, 64, 4);
    extract_patches_kernel<<<B, block>>>(img, pos, out);
}